// round 1
// baseline (speedup 1.0000x reference)
#include <cuda_runtime.h>

#define N_NODES 100000
#define N_EDGES 3200000
#define D 128

// Scratch for the transformed features Y = F @ W^T  (51.2 MB, static device global)
__device__ float g_Y[(size_t)N_NODES * D];

// ---------------------------------------------------------------------------
// Kernel 1: out[n][c] = bias[c]   (output is poisoned by the harness)
// ---------------------------------------------------------------------------
__global__ void init_bias_kernel(float* __restrict__ out, const float* __restrict__ bias) {
    int i = blockIdx.x * blockDim.x + threadIdx.x;        // float4 index
    const int total = N_NODES * (D / 4);                  // 3.2M float4
    if (i < total) {
        const float4* b4 = (const float4*)bias;           // 32 float4
        ((float4*)out)[i] = b4[i & 31];
    }
}

// ---------------------------------------------------------------------------
// Kernel 2: Y[m][c] = sum_k F[m][k] * W[c][k]      (M=100000, K=N=128)
// 128x128 block tile, BK=16, 8x8 register tile, 256 threads.
// ---------------------------------------------------------------------------
__global__ __launch_bounds__(256) void gemm_kernel(const float* __restrict__ F,
                                                   const float* __restrict__ W) {
    const int BM = 128, BN = 128, BK = 16, TM = 8, TN = 8;
    __shared__ float Fs[BK][BM];
    __shared__ float Ws[BK][BN];

    const int tid = threadIdx.x;
    const int tn = (tid % 16) * TN;
    const int tm = (tid / 16) * TM;
    const int m0 = blockIdx.x * BM;

    float acc[TM][TN];
#pragma unroll
    for (int i = 0; i < TM; i++)
#pragma unroll
        for (int j = 0; j < TN; j++) acc[i][j] = 0.0f;

    for (int kt = 0; kt < D; kt += BK) {
        // Load F tile (128 rows x 16 cols) into Fs[k][m] (transposed)
#pragma unroll
        for (int l = 0; l < 2; l++) {
            int idx = tid * 2 + l;          // 512 float4 slots
            int m   = idx >> 2;             // row within tile
            int kq  = idx & 3;              // which float4 of the 16 cols
            float4 v = make_float4(0.f, 0.f, 0.f, 0.f);
            if (m0 + m < N_NODES)
                v = *(const float4*)(F + (size_t)(m0 + m) * D + kt + kq * 4);
            Fs[kq * 4 + 0][m] = v.x;
            Fs[kq * 4 + 1][m] = v.y;
            Fs[kq * 4 + 2][m] = v.z;
            Fs[kq * 4 + 3][m] = v.w;
        }
        // Load W tile: Ws[k][c] = W[c][kt+k]
#pragma unroll
        for (int l = 0; l < 2; l++) {
            int idx = tid * 2 + l;
            int c   = idx >> 2;
            int kq  = idx & 3;
            float4 v = *(const float4*)(W + (size_t)c * D + kt + kq * 4);
            Ws[kq * 4 + 0][c] = v.x;
            Ws[kq * 4 + 1][c] = v.y;
            Ws[kq * 4 + 2][c] = v.z;
            Ws[kq * 4 + 3][c] = v.w;
        }
        __syncthreads();

#pragma unroll
        for (int k = 0; k < BK; k++) {
            float rm[TM], rn[TN];
            // vector loads from smem
            float4 a0 = *(const float4*)&Fs[k][tm];
            float4 a1 = *(const float4*)&Fs[k][tm + 4];
            float4 b0 = *(const float4*)&Ws[k][tn];
            float4 b1 = *(const float4*)&Ws[k][tn + 4];
            rm[0] = a0.x; rm[1] = a0.y; rm[2] = a0.z; rm[3] = a0.w;
            rm[4] = a1.x; rm[5] = a1.y; rm[6] = a1.z; rm[7] = a1.w;
            rn[0] = b0.x; rn[1] = b0.y; rn[2] = b0.z; rn[3] = b0.w;
            rn[4] = b1.x; rn[5] = b1.y; rn[6] = b1.z; rn[7] = b1.w;
#pragma unroll
            for (int i = 0; i < TM; i++)
#pragma unroll
                for (int j = 0; j < TN; j++)
                    acc[i][j] = fmaf(rm[i], rn[j], acc[i][j]);
        }
        __syncthreads();
    }

    // Store Y
#pragma unroll
    for (int i = 0; i < TM; i++) {
        int m = m0 + tm + i;
        if (m < N_NODES) {
#pragma unroll
            for (int j = 0; j < TN; j += 4) {
                *(float4*)(g_Y + (size_t)m * D + tn + j) =
                    make_float4(acc[i][j], acc[i][j + 1], acc[i][j + 2], acc[i][j + 3]);
            }
        }
    }
}

// ---------------------------------------------------------------------------
// Kernel 3: per-edge scatter   out[dst] += norm * Y[src]
// One warp per edge; lane l handles float4 at column 4*l (full 512B row).
// Vector reduction red.global.add.v4.f32 (sm_90+).
// ---------------------------------------------------------------------------
__global__ __launch_bounds__(256) void scatter_kernel(const float* __restrict__ norm,
                                                      const int* __restrict__ src,
                                                      const int* __restrict__ dst,
                                                      float* __restrict__ out) {
    int warp = (blockIdx.x * blockDim.x + threadIdx.x) >> 5;
    int lane = threadIdx.x & 31;
    if (warp >= N_EDGES) return;

    int s   = __ldg(src + warp);
    int d   = __ldg(dst + warp);
    float n = __ldg(norm + warp);

    float4 v = *(const float4*)(g_Y + (size_t)s * D + lane * 4);
    v.x *= n; v.y *= n; v.z *= n; v.w *= n;

    float* p = out + (size_t)d * D + lane * 4;
    asm volatile("red.global.add.v4.f32 [%0], {%1, %2, %3, %4};"
                 :: "l"(p), "f"(v.x), "f"(v.y), "f"(v.z), "f"(v.w)
                 : "memory");
}

// ---------------------------------------------------------------------------
extern "C" void kernel_launch(void* const* d_in, const int* in_sizes, int n_in,
                              void* d_out, int out_size) {
    const float* features = (const float*)d_in[0];
    const float* norm     = (const float*)d_in[1];
    const int*   src      = (const int*)d_in[2];
    const int*   dst      = (const int*)d_in[3];
    const float* weight   = (const float*)d_in[4];
    const float* bias     = (const float*)d_in[5];
    float*       out      = (float*)d_out;

    // 1) out = bias (broadcast)
    {
        int total = N_NODES * (D / 4);
        int threads = 256;
        int blocks = (total + threads - 1) / threads;
        init_bias_kernel<<<blocks, threads>>>(out, bias);
    }
    // 2) Y = F @ W^T
    {
        int blocks = (N_NODES + 127) / 128;
        gemm_kernel<<<blocks, 256>>>(features, weight);
    }
    // 3) out[dst] += norm * Y[src]
    {
        long long total_threads = (long long)N_EDGES * 32;
        int threads = 256;
        int blocks = (int)((total_threads + threads - 1) / threads);
        scatter_kernel<<<blocks, threads>>>(norm, src, dst, out);
    }
}

// round 3
// speedup vs baseline: 1.1550x; 1.1550x over previous
#include <cuda_runtime.h>

#define N_NODES 100000
#define N_EDGES 3200000
#define D 128

// ---------------- static device scratch (no allocation allowed) ----------------
__device__ float g_Y[(size_t)N_NODES * D];       // F @ W^T          (51.2 MB)
__device__ int2  g_edge[N_EDGES];                // {src, norm-bits} (25.6 MB)
__device__ int   g_cnt[N_NODES];                 // histogram
__device__ int   g_off[N_NODES + 1];             // CSR offsets
__device__ int   g_cur[N_NODES];                 // fill cursors

// ---------------------------------------------------------------------------
// Kernel 1: zero histogram
// ---------------------------------------------------------------------------
__global__ void zero_cnt_kernel() {
    int i = blockIdx.x * blockDim.x + threadIdx.x;
    if (i < N_NODES) g_cnt[i] = 0;
}

// ---------------------------------------------------------------------------
// Kernel 2: histogram of dst
// ---------------------------------------------------------------------------
__global__ __launch_bounds__(256) void hist_kernel(const int* __restrict__ dst) {
    int i = blockIdx.x * blockDim.x + threadIdx.x;
    if (i < N_EDGES) atomicAdd(&g_cnt[__ldg(dst + i)], 1);
}

// ---------------------------------------------------------------------------
// Kernel 3: exclusive scan over 100k counters, single block of 1024 threads.
// Each thread serially sums a chunk, block-scan of chunk sums, write back.
// Also initializes cursors = offsets.
// ---------------------------------------------------------------------------
__global__ __launch_bounds__(1024) void scan_kernel() {
    const int P = (N_NODES + 1023) / 1024;   // 98 elements per thread
    int tid = threadIdx.x;
    int base = tid * P;

    int s = 0;
    for (int i = 0; i < P; i++) {
        int idx = base + i;
        if (idx < N_NODES) s += g_cnt[idx];
    }

    __shared__ int sh[1024];
    sh[tid] = s;
    __syncthreads();
    // Hillis-Steele inclusive scan
    for (int off = 1; off < 1024; off <<= 1) {
        int v = (tid >= off) ? sh[tid - off] : 0;
        __syncthreads();
        sh[tid] += v;
        __syncthreads();
    }
    int run = sh[tid] - s;   // exclusive prefix of this chunk

    for (int i = 0; i < P; i++) {
        int idx = base + i;
        if (idx < N_NODES) {
            g_off[idx] = run;
            g_cur[idx] = run;
            run += g_cnt[idx];
        }
    }
    if (tid == 1023) g_off[N_NODES] = run;
}

// ---------------------------------------------------------------------------
// Kernel 4: fill CSR edge list: g_edge[pos] = {src, norm_bits}
// ---------------------------------------------------------------------------
__global__ __launch_bounds__(256) void fill_kernel(const int* __restrict__ src,
                                                   const int* __restrict__ dst,
                                                   const float* __restrict__ norm) {
    int i = blockIdx.x * blockDim.x + threadIdx.x;
    if (i < N_EDGES) {
        int d = __ldg(dst + i);
        int pos = atomicAdd(&g_cur[d], 1);
        g_edge[pos] = make_int2(__ldg(src + i), __float_as_int(__ldg(norm + i)));
    }
}

// ---------------------------------------------------------------------------
// Kernel 5: Y = F @ W^T   (M=100000, K=N=128) — 128x128 tile, BK=16, 8x8/thread
// ---------------------------------------------------------------------------
__global__ __launch_bounds__(256) void gemm_kernel(const float* __restrict__ F,
                                                   const float* __restrict__ W) {
    const int BM = 128, BK = 16, TM = 8, TN = 8;
    __shared__ float Fs[BK][BM];
    __shared__ float Ws[BK][BM];

    const int tid = threadIdx.x;
    const int tn = (tid % 16) * TN;
    const int tm = (tid / 16) * TM;
    const int m0 = blockIdx.x * BM;

    float acc[TM][TN];
#pragma unroll
    for (int i = 0; i < TM; i++)
#pragma unroll
        for (int j = 0; j < TN; j++) acc[i][j] = 0.0f;

    for (int kt = 0; kt < D; kt += BK) {
#pragma unroll
        for (int l = 0; l < 2; l++) {
            int idx = tid * 2 + l;
            int m   = idx >> 2;
            int kq  = idx & 3;
            float4 v = make_float4(0.f, 0.f, 0.f, 0.f);
            if (m0 + m < N_NODES)
                v = *(const float4*)(F + (size_t)(m0 + m) * D + kt + kq * 4);
            Fs[kq * 4 + 0][m] = v.x;
            Fs[kq * 4 + 1][m] = v.y;
            Fs[kq * 4 + 2][m] = v.z;
            Fs[kq * 4 + 3][m] = v.w;
        }
#pragma unroll
        for (int l = 0; l < 2; l++) {
            int idx = tid * 2 + l;
            int c   = idx >> 2;
            int kq  = idx & 3;
            float4 v = *(const float4*)(W + (size_t)c * D + kt + kq * 4);
            Ws[kq * 4 + 0][c] = v.x;
            Ws[kq * 4 + 1][c] = v.y;
            Ws[kq * 4 + 2][c] = v.z;
            Ws[kq * 4 + 3][c] = v.w;
        }
        __syncthreads();

#pragma unroll
        for (int k = 0; k < BK; k++) {
            float rm[TM], rn[TN];
            float4 a0 = *(const float4*)&Fs[k][tm];
            float4 a1 = *(const float4*)&Fs[k][tm + 4];
            float4 b0 = *(const float4*)&Ws[k][tn];
            float4 b1 = *(const float4*)&Ws[k][tn + 4];
            rm[0] = a0.x; rm[1] = a0.y; rm[2] = a0.z; rm[3] = a0.w;
            rm[4] = a1.x; rm[5] = a1.y; rm[6] = a1.z; rm[7] = a1.w;
            rn[0] = b0.x; rn[1] = b0.y; rn[2] = b0.z; rn[3] = b0.w;
            rn[4] = b1.x; rn[5] = b1.y; rn[6] = b1.z; rn[7] = b1.w;
#pragma unroll
            for (int i = 0; i < TM; i++)
#pragma unroll
                for (int j = 0; j < TN; j++)
                    acc[i][j] = fmaf(rm[i], rn[j], acc[i][j]);
        }
        __syncthreads();
    }

#pragma unroll
    for (int i = 0; i < TM; i++) {
        int m = m0 + tm + i;
        if (m < N_NODES) {
#pragma unroll
            for (int j = 0; j < TN; j += 4) {
                *(float4*)(g_Y + (size_t)m * D + tn + j) =
                    make_float4(acc[i][j], acc[i][j + 1], acc[i][j + 2], acc[i][j + 3]);
            }
        }
    }
}

// ---------------------------------------------------------------------------
// Kernel 6: per-node reduction. One warp per node; lane l owns columns 4l..4l+3.
// out[n] = sum_{e in CSR[n]} norm_e * Y[src_e] + bias
// ---------------------------------------------------------------------------
__global__ __launch_bounds__(256) void reduce_kernel(float* __restrict__ out,
                                                     const float* __restrict__ bias) {
    int warp = (blockIdx.x * blockDim.x + threadIdx.x) >> 5;
    int lane = threadIdx.x & 31;
    if (warp >= N_NODES) return;

    int beg = __ldg(&g_off[warp]);
    int end = __ldg(&g_off[warp + 1]);

    float4 acc = make_float4(0.f, 0.f, 0.f, 0.f);

    int e = beg;
    // unrolled by 4 for memory-level parallelism against L2 latency
    for (; e + 3 < end; e += 4) {
        int2 p0 = __ldg(&g_edge[e + 0]);
        int2 p1 = __ldg(&g_edge[e + 1]);
        int2 p2 = __ldg(&g_edge[e + 2]);
        int2 p3 = __ldg(&g_edge[e + 3]);
        float4 v0 = *(const float4*)(g_Y + (size_t)p0.x * D + lane * 4);
        float4 v1 = *(const float4*)(g_Y + (size_t)p1.x * D + lane * 4);
        float4 v2 = *(const float4*)(g_Y + (size_t)p2.x * D + lane * 4);
        float4 v3 = *(const float4*)(g_Y + (size_t)p3.x * D + lane * 4);
        float n0 = __int_as_float(p0.y);
        float n1 = __int_as_float(p1.y);
        float n2 = __int_as_float(p2.y);
        float n3 = __int_as_float(p3.y);
        acc.x = fmaf(n0, v0.x, acc.x); acc.y = fmaf(n0, v0.y, acc.y);
        acc.z = fmaf(n0, v0.z, acc.z); acc.w = fmaf(n0, v0.w, acc.w);
        acc.x = fmaf(n1, v1.x, acc.x); acc.y = fmaf(n1, v1.y, acc.y);
        acc.z = fmaf(n1, v1.z, acc.z); acc.w = fmaf(n1, v1.w, acc.w);
        acc.x = fmaf(n2, v2.x, acc.x); acc.y = fmaf(n2, v2.y, acc.y);
        acc.z = fmaf(n2, v2.z, acc.z); acc.w = fmaf(n2, v2.w, acc.w);
        acc.x = fmaf(n3, v3.x, acc.x); acc.y = fmaf(n3, v3.y, acc.y);
        acc.z = fmaf(n3, v3.z, acc.z); acc.w = fmaf(n3, v3.w, acc.w);
    }
    for (; e < end; e++) {
        int2 p = __ldg(&g_edge[e]);
        float nv = __int_as_float(p.y);
        float4 v = *(const float4*)(g_Y + (size_t)p.x * D + lane * 4);
        acc.x = fmaf(nv, v.x, acc.x); acc.y = fmaf(nv, v.y, acc.y);
        acc.z = fmaf(nv, v.z, acc.z); acc.w = fmaf(nv, v.w, acc.w);
    }

    float4 b = ((const float4*)bias)[lane];
    acc.x += b.x; acc.y += b.y; acc.z += b.z; acc.w += b.w;
    *(float4*)(out + (size_t)warp * D + lane * 4) = acc;
}

// ---------------------------------------------------------------------------
extern "C" void kernel_launch(void* const* d_in, const int* in_sizes, int n_in,
                              void* d_out, int out_size) {
    const float* features = (const float*)d_in[0];
    const float* norm     = (const float*)d_in[1];
    const int*   src      = (const int*)d_in[2];
    const int*   dst      = (const int*)d_in[3];
    const float* weight   = (const float*)d_in[4];
    const float* bias     = (const float*)d_in[5];
    float*       out      = (float*)d_out;

    zero_cnt_kernel<<<(N_NODES + 255) / 256, 256>>>();
    hist_kernel<<<(N_EDGES + 255) / 256, 256>>>(dst);
    scan_kernel<<<1, 1024>>>();
    fill_kernel<<<(N_EDGES + 255) / 256, 256>>>(src, dst, norm);
    gemm_kernel<<<(N_NODES + 127) / 128, 256>>>(features, weight);

    long long total_threads = (long long)N_NODES * 32;
    reduce_kernel<<<(int)((total_threads + 255) / 256), 256>>>(out, bias);
}

// round 4
// speedup vs baseline: 1.2851x; 1.1126x over previous
#include <cuda_runtime.h>
#include <cuda_fp16.h>

#define N_NODES 100000
#define N_EDGES 3200000
#define D 128

// ---------------- static device scratch (no allocation allowed) ----------------
__device__ __half g_Y[(size_t)N_NODES * D];      // F @ W^T in fp16  (25.6 MB)
__device__ int2   g_edge[N_EDGES];               // {src, norm-bits} (25.6 MB)
__device__ int    g_cnt[N_NODES];                // histogram
__device__ int    g_off[N_NODES + 1];            // CSR offsets
__device__ int    g_cur[N_NODES];                // fill cursors

// ---------------------------------------------------------------------------
// Kernel 1: zero histogram
// ---------------------------------------------------------------------------
__global__ void zero_cnt_kernel() {
    int i = blockIdx.x * blockDim.x + threadIdx.x;
    if (i < N_NODES) g_cnt[i] = 0;
}

// ---------------------------------------------------------------------------
// Kernel 2: histogram of dst
// ---------------------------------------------------------------------------
__global__ __launch_bounds__(256) void hist_kernel(const int* __restrict__ dst) {
    int i = blockIdx.x * blockDim.x + threadIdx.x;
    if (i < N_EDGES) atomicAdd(&g_cnt[__ldg(dst + i)], 1);
}

// ---------------------------------------------------------------------------
// Kernel 3: exclusive scan over 100k counters, single block of 1024 threads.
// ---------------------------------------------------------------------------
__global__ __launch_bounds__(1024) void scan_kernel() {
    const int P = (N_NODES + 1023) / 1024;   // 98 elements per thread
    int tid = threadIdx.x;
    int base = tid * P;

    int s = 0;
    for (int i = 0; i < P; i++) {
        int idx = base + i;
        if (idx < N_NODES) s += g_cnt[idx];
    }

    __shared__ int sh[1024];
    sh[tid] = s;
    __syncthreads();
    for (int off = 1; off < 1024; off <<= 1) {
        int v = (tid >= off) ? sh[tid - off] : 0;
        __syncthreads();
        sh[tid] += v;
        __syncthreads();
    }
    int run = sh[tid] - s;   // exclusive prefix of this chunk

    for (int i = 0; i < P; i++) {
        int idx = base + i;
        if (idx < N_NODES) {
            g_off[idx] = run;
            g_cur[idx] = run;
            run += g_cnt[idx];
        }
    }
    if (tid == 1023) g_off[N_NODES] = run;
}

// ---------------------------------------------------------------------------
// Kernel 4: fill CSR edge list: g_edge[pos] = {src, norm_bits}
// ---------------------------------------------------------------------------
__global__ __launch_bounds__(256) void fill_kernel(const int* __restrict__ src,
                                                   const int* __restrict__ dst,
                                                   const float* __restrict__ norm) {
    int i = blockIdx.x * blockDim.x + threadIdx.x;
    if (i < N_EDGES) {
        int d = __ldg(dst + i);
        int pos = atomicAdd(&g_cur[d], 1);
        g_edge[pos] = make_int2(__ldg(src + i), __float_as_int(__ldg(norm + i)));
    }
}

// ---------------------------------------------------------------------------
// Kernel 5: Y = F @ W^T   (fp32 compute, fp16 store)
// 128x128 tile, BK=16, 8x8 register tile, 256 threads.
// ---------------------------------------------------------------------------
__global__ __launch_bounds__(256) void gemm_kernel(const float* __restrict__ F,
                                                   const float* __restrict__ W) {
    const int BM = 128, BK = 16, TM = 8, TN = 8;
    __shared__ float Fs[BK][BM];
    __shared__ float Ws[BK][BM];

    const int tid = threadIdx.x;
    const int tn = (tid % 16) * TN;
    const int tm = (tid / 16) * TM;
    const int m0 = blockIdx.x * BM;

    float acc[TM][TN];
#pragma unroll
    for (int i = 0; i < TM; i++)
#pragma unroll
        for (int j = 0; j < TN; j++) acc[i][j] = 0.0f;

    for (int kt = 0; kt < D; kt += BK) {
#pragma unroll
        for (int l = 0; l < 2; l++) {
            int idx = tid * 2 + l;
            int m   = idx >> 2;
            int kq  = idx & 3;
            float4 v = make_float4(0.f, 0.f, 0.f, 0.f);
            if (m0 + m < N_NODES)
                v = *(const float4*)(F + (size_t)(m0 + m) * D + kt + kq * 4);
            Fs[kq * 4 + 0][m] = v.x;
            Fs[kq * 4 + 1][m] = v.y;
            Fs[kq * 4 + 2][m] = v.z;
            Fs[kq * 4 + 3][m] = v.w;
        }
#pragma unroll
        for (int l = 0; l < 2; l++) {
            int idx = tid * 2 + l;
            int c   = idx >> 2;
            int kq  = idx & 3;
            float4 v = *(const float4*)(W + (size_t)c * D + kt + kq * 4);
            Ws[kq * 4 + 0][c] = v.x;
            Ws[kq * 4 + 1][c] = v.y;
            Ws[kq * 4 + 2][c] = v.z;
            Ws[kq * 4 + 3][c] = v.w;
        }
        __syncthreads();

#pragma unroll
        for (int k = 0; k < BK; k++) {
            float rm[TM], rn[TN];
            float4 a0 = *(const float4*)&Fs[k][tm];
            float4 a1 = *(const float4*)&Fs[k][tm + 4];
            float4 b0 = *(const float4*)&Ws[k][tn];
            float4 b1 = *(const float4*)&Ws[k][tn + 4];
            rm[0] = a0.x; rm[1] = a0.y; rm[2] = a0.z; rm[3] = a0.w;
            rm[4] = a1.x; rm[5] = a1.y; rm[6] = a1.z; rm[7] = a1.w;
            rn[0] = b0.x; rn[1] = b0.y; rn[2] = b0.z; rn[3] = b0.w;
            rn[4] = b1.x; rn[5] = b1.y; rn[6] = b1.z; rn[7] = b1.w;
#pragma unroll
            for (int i = 0; i < TM; i++)
#pragma unroll
                for (int j = 0; j < TN; j++)
                    acc[i][j] = fmaf(rm[i], rn[j], acc[i][j]);
        }
        __syncthreads();
    }

    // Store Y as fp16: 8 halves (16B) per row fragment
#pragma unroll
    for (int i = 0; i < TM; i++) {
        int m = m0 + tm + i;
        if (m < N_NODES) {
            __half2 h[4];
#pragma unroll
            for (int j = 0; j < 4; j++)
                h[j] = __floats2half2_rn(acc[i][2 * j], acc[i][2 * j + 1]);
            *(uint4*)(g_Y + (size_t)m * D + tn) = *(uint4*)h;
        }
    }
}

// ---------------------------------------------------------------------------
// Kernel 6: per-node reduction. One warp per node; lane l owns columns 4l..4l+3
// (4 halves = one 8B load). out[n] = sum norm_e * Y[src_e] + bias (fp32 accum)
// ---------------------------------------------------------------------------
__global__ __launch_bounds__(256) void reduce_kernel(float* __restrict__ out,
                                                     const float* __restrict__ bias) {
    int warp = (blockIdx.x * blockDim.x + threadIdx.x) >> 5;
    int lane = threadIdx.x & 31;
    if (warp >= N_NODES) return;

    int beg = __ldg(&g_off[warp]);
    int end = __ldg(&g_off[warp + 1]);

    float4 acc = make_float4(0.f, 0.f, 0.f, 0.f);
    const __half* Ybase = g_Y;

    int e = beg;
    for (; e + 3 < end; e += 4) {
        int2 p0 = __ldg(&g_edge[e + 0]);
        int2 p1 = __ldg(&g_edge[e + 1]);
        int2 p2 = __ldg(&g_edge[e + 2]);
        int2 p3 = __ldg(&g_edge[e + 3]);
        uint2 u0 = *(const uint2*)(Ybase + (size_t)p0.x * D + lane * 4);
        uint2 u1 = *(const uint2*)(Ybase + (size_t)p1.x * D + lane * 4);
        uint2 u2 = *(const uint2*)(Ybase + (size_t)p2.x * D + lane * 4);
        uint2 u3 = *(const uint2*)(Ybase + (size_t)p3.x * D + lane * 4);
        float n0 = __int_as_float(p0.y);
        float n1 = __int_as_float(p1.y);
        float n2 = __int_as_float(p2.y);
        float n3 = __int_as_float(p3.y);

        float2 a, b;
        a = __half22float2(*(__half2*)&u0.x); b = __half22float2(*(__half2*)&u0.y);
        acc.x = fmaf(n0, a.x, acc.x); acc.y = fmaf(n0, a.y, acc.y);
        acc.z = fmaf(n0, b.x, acc.z); acc.w = fmaf(n0, b.y, acc.w);
        a = __half22float2(*(__half2*)&u1.x); b = __half22float2(*(__half2*)&u1.y);
        acc.x = fmaf(n1, a.x, acc.x); acc.y = fmaf(n1, a.y, acc.y);
        acc.z = fmaf(n1, b.x, acc.z); acc.w = fmaf(n1, b.y, acc.w);
        a = __half22float2(*(__half2*)&u2.x); b = __half22float2(*(__half2*)&u2.y);
        acc.x = fmaf(n2, a.x, acc.x); acc.y = fmaf(n2, a.y, acc.y);
        acc.z = fmaf(n2, b.x, acc.z); acc.w = fmaf(n2, b.y, acc.w);
        a = __half22float2(*(__half2*)&u3.x); b = __half22float2(*(__half2*)&u3.y);
        acc.x = fmaf(n3, a.x, acc.x); acc.y = fmaf(n3, a.y, acc.y);
        acc.z = fmaf(n3, b.x, acc.z); acc.w = fmaf(n3, b.y, acc.w);
    }
    for (; e < end; e++) {
        int2 p = __ldg(&g_edge[e]);
        float nv = __int_as_float(p.y);
        uint2 u = *(const uint2*)(Ybase + (size_t)p.x * D + lane * 4);
        float2 a = __half22float2(*(__half2*)&u.x);
        float2 b = __half22float2(*(__half2*)&u.y);
        acc.x = fmaf(nv, a.x, acc.x); acc.y = fmaf(nv, a.y, acc.y);
        acc.z = fmaf(nv, b.x, acc.z); acc.w = fmaf(nv, b.y, acc.w);
    }

    float4 bb = ((const float4*)bias)[lane];
    acc.x += bb.x; acc.y += bb.y; acc.z += bb.z; acc.w += bb.w;
    *(float4*)(out + (size_t)warp * D + lane * 4) = acc;
}

// ---------------------------------------------------------------------------
extern "C" void kernel_launch(void* const* d_in, const int* in_sizes, int n_in,
                              void* d_out, int out_size) {
    const float* features = (const float*)d_in[0];
    const float* norm     = (const float*)d_in[1];
    const int*   src      = (const int*)d_in[2];
    const int*   dst      = (const int*)d_in[3];
    const float* weight   = (const float*)d_in[4];
    const float* bias     = (const float*)d_in[5];
    float*       out      = (float*)d_out;

    zero_cnt_kernel<<<(N_NODES + 255) / 256, 256>>>();
    hist_kernel<<<(N_EDGES + 255) / 256, 256>>>(dst);
    scan_kernel<<<1, 1024>>>();
    fill_kernel<<<(N_EDGES + 255) / 256, 256>>>(src, dst, norm);
    gemm_kernel<<<(N_NODES + 127) / 128, 256>>>(features, weight);

    long long total_threads = (long long)N_NODES * 32;
    reduce_kernel<<<(int)((total_threads + 255) / 256), 256>>>(out, bias);
}